// round 8
// baseline (speedup 1.0000x reference)
#include <cuda_runtime.h>

#define DD 13
#define HH 32
#define FF 45
#define XP 16
#define K1 64
#define GG 128
#define NMAX 50000
#define WABROW 92
#define TILE 128
#define H1S 36    // floats per staged half-row (32 + 4 pad) -> conflict-free LDS.128

typedef unsigned long long ull;
typedef unsigned int u32;

// ---------------- device scratch ----------------
__device__ float g_sum[DD];
__device__ float g_sumsq[DD];
__device__ float g_mean[DD];
__device__ float g_istd[DD];
__device__ float g_X[NMAX * XP];
__device__ float g_u[NMAX * K1];
__device__ float g_v[NMAX * K1];
__device__ float g_acc[NMAX * HH];
__device__ float g_wab[K1 * WABROW];
__device__ float g_gsum[GG * (HH + XP)];
__device__ int   g_gcnt[GG];

// ---------------- helpers ----------------
__device__ __forceinline__ float tanh_fast(float x) {
    float y; asm("tanh.approx.f32 %0, %1;" : "=f"(y) : "f"(x)); return y;
}
__device__ __forceinline__ void red_add_v4(float* p, float a, float b, float c, float d) {
    asm volatile("red.global.add.v4.f32 [%0], {%1, %2, %3, %4};"
                 :: "l"(p), "f"(a), "f"(b), "f"(c), "f"(d) : "memory");
}
__device__ __forceinline__ ull pack2(float x) {
    ull r; asm("mov.b64 %0, {%1, %1};" : "=l"(r) : "r"(__float_as_uint(x))); return r;
}
__device__ __forceinline__ void ffma2(ull& d, ull a, ull b) {
    asm("fma.rn.f32x2 %0, %1, %2, %0;" : "+l"(d) : "l"(a), "l"(b));
}
__device__ __forceinline__ ull add2(ull a, ull b) {
    ull r; asm("add.rn.f32x2 %0, %1, %2;" : "=l"(r) : "l"(a), "l"(b)); return r;
}
__device__ __forceinline__ void unpack2(ull v, float& lo, float& hi) {
    u32 a, b; asm("mov.b64 {%0, %1}, %2;" : "=r"(a), "=r"(b) : "l"(v));
    lo = __uint_as_float(a); hi = __uint_as_float(b);
}

// ---------------- 1) small zero ----------------
__global__ void zero_kernel() {
    int i = threadIdx.x;
    if (i < DD) { g_sum[i] = 0.f; g_sumsq[i] = 0.f; }
    for (int j = i; j < GG * (HH + XP); j += blockDim.x) g_gsum[j] = 0.f;
    if (i < GG) g_gcnt[i] = 0;
}

// ---------------- 2) batchnorm statistics ----------------
__global__ void bn_stats(const float* __restrict__ x, int n) {
    float s[DD], s2[DD];
#pragma unroll
    for (int d = 0; d < DD; d++) { s[d] = 0.f; s2[d] = 0.f; }
    for (int i = blockIdx.x * blockDim.x + threadIdx.x; i < n;
         i += gridDim.x * blockDim.x) {
#pragma unroll
        for (int d = 0; d < DD; d++) {
            float v = x[i * DD + d];
            s[d] += v; s2[d] += v * v;
        }
    }
#pragma unroll
    for (int d = 0; d < DD; d++) {
        for (int off = 16; off > 0; off >>= 1) {
            s[d]  += __shfl_down_sync(0xffffffffu, s[d], off);
            s2[d] += __shfl_down_sync(0xffffffffu, s2[d], off);
        }
    }
    if ((threadIdx.x & 31) == 0) {
#pragma unroll
        for (int d = 0; d < DD; d++) {
            atomicAdd(&g_sum[d], s[d]);
            atomicAdd(&g_sumsq[d], s2[d]);
        }
    }
}

// ---------------- 3) prep: stats + interleaved combined conv_w1 ----------------
__global__ void prep_kernel(const float* __restrict__ conv_w1, float invN) {
    int tid = threadIdx.x;
    if (tid < DD) {
        float mu  = g_sum[tid] * invN;
        float var = g_sumsq[tid] * invN - mu * mu;
        g_mean[tid] = mu;
        g_istd[tid] = rsqrtf(var + 1e-5f);
    }
    for (int i = tid; i < K1 * (WABROW / 2); i += blockDim.x) {
        int k = i / (WABROW / 2), a = i % (WABROW / 2);
        float wa = 0.f, wb = 0.f;
        if (a < FF) {
            float w0 = conv_w1[a * K1 + k];
            float w1 = conv_w1[(FF + a) * K1 + k];
            wa = w0 - w1; wb = w1;
        }
        g_wab[k * WABROW + 2 * a]     = wa;
        g_wab[k * WABROW + 2 * a + 1] = wb;
    }
}

// ---------------- 4) node kernel: BN + inputnet + packed u/v + zero acc ----------------
__global__ void node_kernel(const float* __restrict__ x,
                            const float* __restrict__ gamma,
                            const float* __restrict__ beta,
                            const float* __restrict__ w1,
                            const float* __restrict__ b1,
                            const float* __restrict__ w2,
                            const float* __restrict__ b2,
                            const float* __restrict__ conv_b1,
                            int n) {
    __shared__ float s_w1[DD * HH], s_w2[HH * HH], s_b1[HH], s_b2[HH];
    __shared__ float s_gam[DD], s_bet[DD], s_mu[DD], s_is[DD];
    __shared__ float s_wab[K1 * WABROW];
    __shared__ ull   s_cbp[K1];
    for (int i = threadIdx.x; i < DD * HH; i += blockDim.x) s_w1[i] = w1[i];
    for (int i = threadIdx.x; i < HH * HH; i += blockDim.x) s_w2[i] = w2[i];
    for (int i = threadIdx.x; i < K1 * WABROW; i += blockDim.x) s_wab[i] = g_wab[i];
    if (threadIdx.x < K1)
        s_cbp[threadIdx.x] = (ull)__float_as_uint(conv_b1[threadIdx.x]);
    if (threadIdx.x < HH) { s_b1[threadIdx.x] = b1[threadIdx.x]; s_b2[threadIdx.x] = b2[threadIdx.x]; }
    if (threadIdx.x < DD) {
        s_gam[threadIdx.x] = gamma[threadIdx.x];
        s_bet[threadIdx.x] = beta[threadIdx.x];
        s_mu[threadIdx.x]  = g_mean[threadIdx.x];
        s_is[threadIdx.x]  = g_istd[threadIdx.x];
    }
    __syncthreads();
    int nn = blockIdx.x * blockDim.x + threadIdx.x;
    if (nn >= n) return;

    float X[DD];
#pragma unroll
    for (int d = 0; d < DD; d++)
        X[d] = (x[nn * DD + d] - s_mu[d]) * s_is[d] * s_gam[d] + s_bet[d];

    float h[HH];
#pragma unroll
    for (int j = 0; j < HH; j++) {
        float t = s_b1[j];
#pragma unroll
        for (int d = 0; d < DD; d++) t = fmaf(X[d], s_w1[d * HH + j], t);
        h[j] = fmaxf(t, 0.f);
    }
    ull fp[FF];
#pragma unroll
    for (int j = 0; j < HH; j++) {
        float t = s_b2[j];
#pragma unroll
        for (int k = 0; k < HH; k++) t = fmaf(h[k], s_w2[k * HH + j], t);
        fp[j] = pack2(tanh_fast(t));
    }
#pragma unroll
    for (int d = 0; d < DD; d++) fp[HH + d] = pack2(X[d]);

    float* xp = g_X + (size_t)nn * XP;
#pragma unroll
    for (int d = 0; d < DD; d++) xp[d] = X[d];
    xp[13] = 0.f; xp[14] = 0.f; xp[15] = 0.f;

    // zero this node's accumulator row
    float4 z = make_float4(0.f, 0.f, 0.f, 0.f);
    float4* ar = (float4*)(g_acc + (size_t)nn * HH);
#pragma unroll
    for (int q = 0; q < 8; q++) ar[q] = z;

    float* up = g_u + (size_t)nn * K1;
    float* vp = g_v + (size_t)nn * K1;
#pragma unroll 1
    for (int k4 = 0; k4 < K1 / 4; k4++) {
        float uu[4], vv[4];
#pragma unroll
        for (int j = 0; j < 4; j++) {
            int k = 4 * k4 + j;
            ull a0 = s_cbp[k], a1 = 0ULL;
            const ulonglong2* wr = (const ulonglong2*)(s_wab + k * WABROW);
#pragma unroll
            for (int q = 0; q < 22; q++) {
                ulonglong2 w = wr[q];
                ffma2(a0, fp[2 * q], w.x);
                ffma2(a1, fp[2 * q + 1], w.y);
            }
            ull wl = ((const ull*)(s_wab + k * WABROW))[44];
            ffma2(a0, fp[44], wl);
            unpack2(add2(a0, a1), uu[j], vv[j]);
        }
        *(float4*)(up + 4 * k4) = make_float4(uu[0], uu[1], uu[2], uu[3]);
        *(float4*)(vp + 4 * k4) = make_float4(vv[0], vv[1], vv[2], vv[3]);
    }
}

// ---------------- 5) edge kernel: k-split staging, 8 CTAs/SM ----------------
__global__ void __launch_bounds__(128, 8)
edge_kernel(const int* __restrict__ ei,
            const float* __restrict__ conv_w2,
            const float* __restrict__ conv_b2,
            int E, int ntiles) {
    __shared__ float s_h1[TILE * H1S];        // 18432 B, warp-local rows
    __shared__ float s_w2[K1 * HH];           // 8192 B
    __shared__ ull   s_b2p[HH / 2];

    int tid = threadIdx.x;
    int wid = tid >> 5, lid = tid & 31;
    for (int i = tid; i < K1 * HH; i += 128) s_w2[i] = conv_w2[i];
    if (tid < HH / 2) s_b2p[tid] = ((const ull*)conv_b2)[tid];
    __syncthreads();

    int g8 = lid >> 3;       // row group (0..3)
    int c8 = lid & 7;        // float4 chunk within half-row (0..7)

    for (int tile = blockIdx.x; tile < ntiles; tile += gridDim.x) {
        int base = tile * TILE;
        int e = base + tid;
        bool val = e < E;
        int msrc = val ? ei[e] : 0;
        int mdst = val ? ei[E + e] : 0;

        ull h2[16];
#pragma unroll
        for (int q = 0; q < 16; q++) h2[q] = s_b2p[q];

#pragma unroll
        for (int half = 0; half < 2; half++) {
            // ---- stage this warp's 32 half-rows (4 rows/step, coalesced) ----
#pragma unroll
            for (int s = 0; s < 8; s++) {
                int r = 4 * s + g8;                 // row within warp
                int dn = __shfl_sync(0xffffffffu, mdst, r);
                int sn = __shfl_sync(0xffffffffu, msrc, r);
                float4 U = ((const float4*)(g_u + (size_t)dn * K1 + half * 32))[c8];
                float4 V = ((const float4*)(g_v + (size_t)sn * K1 + half * 32))[c8];
                float4 o;
                o.x = fmaxf(U.x + V.x, 0.f);
                o.y = fmaxf(U.y + V.y, 0.f);
                o.z = fmaxf(U.z + V.z, 0.f);
                o.w = fmaxf(U.w + V.w, 0.f);
                *(float4*)(s_h1 + ((wid << 5) + r) * H1S + 4 * c8) = o;
            }
            __syncwarp();

            // ---- compute this half's 32 k-terms for this thread's edge ----
            const float* hrow = s_h1 + tid * H1S;
#pragma unroll
            for (int q = 0; q < 8; q++) {
                float4 hq = *(const float4*)(hrow + 4 * q);
#pragma unroll
                for (int j = 0; j < 4; j++) {
                    int k = (half << 5) + 4 * q + j;
                    float t = (j == 0) ? hq.x : (j == 1) ? hq.y : (j == 2) ? hq.z : hq.w;
                    ull tp = pack2(t);
                    const ulonglong2* wr = (const ulonglong2*)(s_w2 + (k << 5));
#pragma unroll
                    for (int i = 0; i < 8; i++) {
                        ulonglong2 w = wr[i];
                        ffma2(h2[2 * i],     tp, w.x);
                        ffma2(h2[2 * i + 1], tp, w.y);
                    }
                }
            }
            __syncwarp();   // lanes done reading before next restage
        }

        if (val) {
            float* ap = g_acc + (size_t)mdst * HH;
#pragma unroll
            for (int q = 0; q < 8; q++) {
                float a, b, c, d;
                unpack2(h2[2 * q], a, b);
                unpack2(h2[2 * q + 1], c, d);
                red_add_v4(ap + 4 * q, tanh_fast(a), tanh_fast(b),
                           tanh_fast(c), tanh_fast(d));
            }
        }
    }
}

// ---------------- 6) global mean pool ----------------
__global__ void pool_kernel(const int* __restrict__ batch, int n) {
    int nn = blockIdx.x * blockDim.x + threadIdx.x;
    if (nn >= n) return;
    int g = batch[nn];
    const float4* ac = (const float4*)(g_acc + (size_t)nn * HH);
    const float4* xr = (const float4*)(g_X + (size_t)nn * XP);
    float* gs = g_gsum + (size_t)g * (HH + XP);
#pragma unroll
    for (int q = 0; q < 8; q++) {
        float4 v = ac[q];
        red_add_v4(gs + 4 * q, v.x, v.y, v.z, v.w);
    }
#pragma unroll
    for (int q = 0; q < 4; q++) {
        float4 v = xr[q];
        red_add_v4(gs + HH + 4 * q, v.x, v.y, v.z, v.w);
    }
    atomicAdd(&g_gcnt[g], 1);
}

// ---------------- 7) output MLP + sigmoid ----------------
__global__ void out_kernel(const float* __restrict__ w1,
                           const float* __restrict__ b1,
                           const float* __restrict__ w2,
                           const float* __restrict__ b2,
                           float* __restrict__ out, int gcount) {
    int g = blockIdx.x * blockDim.x + threadIdx.x;
    if (g >= gcount) return;
    float cnt = fmaxf((float)g_gcnt[g], 1.f);
    float inv = 1.f / cnt;
    float m[FF];
#pragma unroll
    for (int a = 0; a < FF; a++) m[a] = g_gsum[g * (HH + XP) + a] * inv;
    float o = b2[0];
    for (int h = 0; h < HH; h++) {
        float t = b1[h];
#pragma unroll
        for (int a = 0; a < FF; a++) t = fmaf(m[a], w1[a * HH + h], t);
        o = fmaf(fmaxf(t, 0.f), w2[h], o);
    }
    out[g] = 1.f / (1.f + expf(-o));
}

// ---------------- launch ----------------
extern "C" void kernel_launch(void* const* d_in, const int* in_sizes, int n_in,
                              void* d_out, int out_size) {
    const float* x     = (const float*)d_in[0];
    const int*   ei    = (const int*)d_in[1];
    const int*   batch = (const int*)d_in[2];
    const float* gamma = (const float*)d_in[3];
    const float* beta  = (const float*)d_in[4];
    const float* in_w1 = (const float*)d_in[5];
    const float* in_b1 = (const float*)d_in[6];
    const float* in_w2 = (const float*)d_in[7];
    const float* in_b2 = (const float*)d_in[8];
    const float* cw1   = (const float*)d_in[9];
    const float* cb1   = (const float*)d_in[10];
    const float* cw2   = (const float*)d_in[11];
    const float* cb2   = (const float*)d_in[12];
    const float* ow1   = (const float*)d_in[13];
    const float* ob1   = (const float*)d_in[14];
    const float* ow2   = (const float*)d_in[15];
    const float* ob2   = (const float*)d_in[16];

    int n = in_sizes[0] / DD;
    int E = in_sizes[1] / 2;
    int G = out_size;
    int ntiles = (E + TILE - 1) / TILE;
    int grid = 1184;
    if (grid > ntiles) grid = ntiles;

    zero_kernel<<<1, 256>>>();
    bn_stats<<<148, 256>>>(x, n);
    prep_kernel<<<1, 256>>>(cw1, 1.f / (float)n);
    node_kernel<<<(n + 127) / 128, 128>>>(x, gamma, beta, in_w1, in_b1,
                                          in_w2, in_b2, cb1, n);
    edge_kernel<<<grid, 128>>>(ei, cw2, cb2, E, ntiles);
    pool_kernel<<<(n + 255) / 256, 256>>>(batch, n);
    out_kernel<<<1, 128>>>(ow1, ob1, ow2, ob2, (float*)d_out, G);
}

// round 9
// speedup vs baseline: 1.9140x; 1.9140x over previous
#include <cuda_runtime.h>

#define DD 13
#define HH 32
#define FF 45
#define XP 16
#define K1 64
#define GG 128
#define NMAX 50000
#define WABROW 92
#define TILE 128
#define H1STRIDE 68   // floats per staged h1 row; 68%32==4 -> conflict-free LDS.128

typedef unsigned long long ull;
typedef unsigned int u32;

// ---------------- device scratch ----------------
__device__ float g_sum[DD];
__device__ float g_sumsq[DD];
__device__ float g_mean[DD];
__device__ float g_istd[DD];
__device__ float g_X[NMAX * XP];
__device__ float g_u[NMAX * K1];
__device__ float g_v[NMAX * K1];
__device__ float g_acc[NMAX * HH];
__device__ float g_wab[K1 * WABROW];
__device__ float g_gsum[GG * (HH + XP)];
__device__ int   g_gcnt[GG];

// ---------------- helpers ----------------
__device__ __forceinline__ float tanh_fast(float x) {
    float y; asm("tanh.approx.f32 %0, %1;" : "=f"(y) : "f"(x)); return y;
}
__device__ __forceinline__ void red_add_v4(float* p, float a, float b, float c, float d) {
    asm volatile("red.global.add.v4.f32 [%0], {%1, %2, %3, %4};"
                 :: "l"(p), "f"(a), "f"(b), "f"(c), "f"(d) : "memory");
}
__device__ __forceinline__ ull pack2(float x) {
    ull r; asm("mov.b64 %0, {%1, %1};" : "=l"(r) : "r"(__float_as_uint(x))); return r;
}
__device__ __forceinline__ void ffma2(ull& d, ull a, ull b) {
    asm("fma.rn.f32x2 %0, %1, %2, %0;" : "+l"(d) : "l"(a), "l"(b));
}
__device__ __forceinline__ ull add2(ull a, ull b) {
    ull r; asm("add.rn.f32x2 %0, %1, %2;" : "=l"(r) : "l"(a), "l"(b)); return r;
}
__device__ __forceinline__ void unpack2(ull v, float& lo, float& hi) {
    u32 a, b; asm("mov.b64 {%0, %1}, %2;" : "=r"(a), "=r"(b) : "l"(v));
    lo = __uint_as_float(a); hi = __uint_as_float(b);
}

// ---------------- 1) small zero ----------------
__global__ void zero_kernel() {
    int i = threadIdx.x;
    if (i < DD) { g_sum[i] = 0.f; g_sumsq[i] = 0.f; }
    for (int j = i; j < GG * (HH + XP); j += blockDim.x) g_gsum[j] = 0.f;
    if (i < GG) g_gcnt[i] = 0;
}

// ---------------- 2) batchnorm statistics ----------------
__global__ void bn_stats(const float* __restrict__ x, int n) {
    float s[DD], s2[DD];
#pragma unroll
    for (int d = 0; d < DD; d++) { s[d] = 0.f; s2[d] = 0.f; }
    for (int i = blockIdx.x * blockDim.x + threadIdx.x; i < n;
         i += gridDim.x * blockDim.x) {
#pragma unroll
        for (int d = 0; d < DD; d++) {
            float v = x[i * DD + d];
            s[d] += v; s2[d] += v * v;
        }
    }
#pragma unroll
    for (int d = 0; d < DD; d++) {
        for (int off = 16; off > 0; off >>= 1) {
            s[d]  += __shfl_down_sync(0xffffffffu, s[d], off);
            s2[d] += __shfl_down_sync(0xffffffffu, s2[d], off);
        }
    }
    if ((threadIdx.x & 31) == 0) {
#pragma unroll
        for (int d = 0; d < DD; d++) {
            atomicAdd(&g_sum[d], s[d]);
            atomicAdd(&g_sumsq[d], s2[d]);
        }
    }
}

// ---------------- 3) prep: stats + interleaved combined conv_w1 ----------------
__global__ void prep_kernel(const float* __restrict__ conv_w1, float invN) {
    int tid = threadIdx.x;
    if (tid < DD) {
        float mu  = g_sum[tid] * invN;
        float var = g_sumsq[tid] * invN - mu * mu;
        g_mean[tid] = mu;
        g_istd[tid] = rsqrtf(var + 1e-5f);
    }
    for (int i = tid; i < K1 * (WABROW / 2); i += blockDim.x) {
        int k = i / (WABROW / 2), a = i % (WABROW / 2);
        float wa = 0.f, wb = 0.f;
        if (a < FF) {
            float w0 = conv_w1[a * K1 + k];
            float w1 = conv_w1[(FF + a) * K1 + k];
            wa = w0 - w1; wb = w1;
        }
        g_wab[k * WABROW + 2 * a]     = wa;
        g_wab[k * WABROW + 2 * a + 1] = wb;
    }
}

// ---------------- 4) node kernel: BN + inputnet + packed u/v + zero acc ----------------
__global__ void node_kernel(const float* __restrict__ x,
                            const float* __restrict__ gamma,
                            const float* __restrict__ beta,
                            const float* __restrict__ w1,
                            const float* __restrict__ b1,
                            const float* __restrict__ w2,
                            const float* __restrict__ b2,
                            const float* __restrict__ conv_b1,
                            int n) {
    __shared__ float s_w1[DD * HH], s_w2[HH * HH], s_b1[HH], s_b2[HH];
    __shared__ float s_gam[DD], s_bet[DD], s_mu[DD], s_is[DD];
    __shared__ float s_wab[K1 * WABROW];
    __shared__ ull   s_cbp[K1];
    for (int i = threadIdx.x; i < DD * HH; i += blockDim.x) s_w1[i] = w1[i];
    for (int i = threadIdx.x; i < HH * HH; i += blockDim.x) s_w2[i] = w2[i];
    for (int i = threadIdx.x; i < K1 * WABROW; i += blockDim.x) s_wab[i] = g_wab[i];
    if (threadIdx.x < K1)
        s_cbp[threadIdx.x] = (ull)__float_as_uint(conv_b1[threadIdx.x]);
    if (threadIdx.x < HH) { s_b1[threadIdx.x] = b1[threadIdx.x]; s_b2[threadIdx.x] = b2[threadIdx.x]; }
    if (threadIdx.x < DD) {
        s_gam[threadIdx.x] = gamma[threadIdx.x];
        s_bet[threadIdx.x] = beta[threadIdx.x];
        s_mu[threadIdx.x]  = g_mean[threadIdx.x];
        s_is[threadIdx.x]  = g_istd[threadIdx.x];
    }
    __syncthreads();
    int nn = blockIdx.x * blockDim.x + threadIdx.x;
    if (nn >= n) return;

    float X[DD];
#pragma unroll
    for (int d = 0; d < DD; d++)
        X[d] = (x[nn * DD + d] - s_mu[d]) * s_is[d] * s_gam[d] + s_bet[d];

    float h[HH];
#pragma unroll
    for (int j = 0; j < HH; j++) {
        float t = s_b1[j];
#pragma unroll
        for (int d = 0; d < DD; d++) t = fmaf(X[d], s_w1[d * HH + j], t);
        h[j] = fmaxf(t, 0.f);
    }
    ull fp[FF];
#pragma unroll
    for (int j = 0; j < HH; j++) {
        float t = s_b2[j];
#pragma unroll
        for (int k = 0; k < HH; k++) t = fmaf(h[k], s_w2[k * HH + j], t);
        fp[j] = pack2(tanh_fast(t));
    }
#pragma unroll
    for (int d = 0; d < DD; d++) fp[HH + d] = pack2(X[d]);

    float* xp = g_X + (size_t)nn * XP;
#pragma unroll
    for (int d = 0; d < DD; d++) xp[d] = X[d];
    xp[13] = 0.f; xp[14] = 0.f; xp[15] = 0.f;

    // zero this node's accumulator row
    float4 z = make_float4(0.f, 0.f, 0.f, 0.f);
    float4* ar = (float4*)(g_acc + (size_t)nn * HH);
#pragma unroll
    for (int q = 0; q < 8; q++) ar[q] = z;

    float* up = g_u + (size_t)nn * K1;
    float* vp = g_v + (size_t)nn * K1;
#pragma unroll 1
    for (int k4 = 0; k4 < K1 / 4; k4++) {
        float uu[4], vv[4];
#pragma unroll
        for (int j = 0; j < 4; j++) {
            int k = 4 * k4 + j;
            ull a0 = s_cbp[k], a1 = 0ULL;
            const ulonglong2* wr = (const ulonglong2*)(s_wab + k * WABROW);
#pragma unroll
            for (int q = 0; q < 22; q++) {
                ulonglong2 w = wr[q];
                ffma2(a0, fp[2 * q], w.x);
                ffma2(a1, fp[2 * q + 1], w.y);
            }
            ull wl = ((const ull*)(s_wab + k * WABROW))[44];
            ffma2(a0, fp[44], wl);
            unpack2(add2(a0, a1), uu[j], vv[j]);
        }
        *(float4*)(up + 4 * k4) = make_float4(uu[0], uu[1], uu[2], uu[3]);
        *(float4*)(vp + 4 * k4) = make_float4(vv[0], vv[1], vv[2], vv[3]);
    }
}

// ---------------- 5) edge kernel: 2 threads per edge (output-split), 256 thr/CTA ----------------
// warp w: g = w & 3 (edge group of 32), outhalf = w >> 2 (which 16 outputs)
// warps g and g+4 co-stage the 32 h1 rows of group g (16 rows each), sync via bar 1+g
__global__ void __launch_bounds__(256, 4)
edge_kernel(const int* __restrict__ ei,
            const float* __restrict__ conv_w2,
            const float* __restrict__ conv_b2,
            int E, int ntiles) {
    __shared__ float s_h1[TILE * H1STRIDE];   // 34816 B
    __shared__ float s_w2[K1 * HH];           // 8192 B
    __shared__ ull   s_b2p[HH / 2];

    int tid = threadIdx.x;
    int wid = tid >> 5, lid = tid & 31;
    int g = wid & 3;          // edge group
    int outhalf = wid >> 2;   // 0: outputs 0..15, 1: outputs 16..31
    for (int i = tid; i < K1 * HH; i += 256) s_w2[i] = conv_w2[i];
    if (tid < HH / 2) s_b2p[tid] = ((const ull*)conv_b2)[tid];
    __syncthreads();

    int c4 = lid & 15;        // quad within a row
    int hi16 = lid >> 4;      // which of 2 rows this lane serves per step

    for (int tile = blockIdx.x; tile < ntiles; tile += gridDim.x) {
        int base = tile * TILE + g * 32;
        int e = base + lid;                 // this thread's edge
        bool val = e < E;
        int msrc = val ? ei[e] : 0;
        int mdst = val ? ei[E + e] : 0;

        // ---- stage 16 of the group's 32 rows (rows outhalf*16 .. +15) ----
#pragma unroll 8
        for (int s = 0; s < 8; s++) {
            int rl = outhalf * 16 + 2 * s + hi16;   // row within group (0..31)
            int dn = __shfl_sync(0xffffffffu, mdst, rl);
            int sn = __shfl_sync(0xffffffffu, msrc, rl);
            float4 U = ((const float4*)(g_u + (size_t)dn * K1))[c4];
            float4 V = ((const float4*)(g_v + (size_t)sn * K1))[c4];
            float4 o;
            o.x = fmaxf(U.x + V.x, 0.f);
            o.y = fmaxf(U.y + V.y, 0.f);
            o.z = fmaxf(U.z + V.z, 0.f);
            o.w = fmaxf(U.w + V.w, 0.f);
            *(float4*)(s_h1 + (g * 32 + rl) * H1STRIDE + 4 * c4) = o;
        }
        // sync warp pair {g, g+4} (named barriers 1..4; 0 reserved for __syncthreads)
        asm volatile("bar.sync %0, 64;" :: "r"(1 + g) : "memory");

        // ---- compute 16 outputs (outhalf) for this thread's edge ----
        ull h2[8];
#pragma unroll
        for (int q = 0; q < 8; q++) h2[q] = s_b2p[outhalf * 8 + q];

        const float* hrow = s_h1 + (g * 32 + lid) * H1STRIDE;
        const float* w2h = s_w2 + outhalf * 16;
#pragma unroll 4
        for (int q = 0; q < 16; q++) {
            float4 hq = *(const float4*)(hrow + 4 * q);
#pragma unroll
            for (int j = 0; j < 4; j++) {
                int k = 4 * q + j;
                float t = (j == 0) ? hq.x : (j == 1) ? hq.y : (j == 2) ? hq.z : hq.w;
                ull tp = pack2(t);
                const ulonglong2* wr = (const ulonglong2*)(w2h + (k << 5));
#pragma unroll
                for (int i = 0; i < 4; i++) {
                    ulonglong2 w = wr[i];
                    ffma2(h2[2 * i],     tp, w.x);
                    ffma2(h2[2 * i + 1], tp, w.y);
                }
            }
        }

        if (val) {
            float* ap = g_acc + (size_t)mdst * HH + outhalf * 16;
#pragma unroll
            for (int q = 0; q < 4; q++) {
                float a, b, c, d;
                unpack2(h2[2 * q], a, b);
                unpack2(h2[2 * q + 1], c, d);
                red_add_v4(ap + 4 * q, tanh_fast(a), tanh_fast(b),
                           tanh_fast(c), tanh_fast(d));
            }
        }
        // pair done reading before next restage
        asm volatile("bar.sync %0, 64;" :: "r"(1 + g) : "memory");
    }
}

// ---------------- 6) global mean pool ----------------
__global__ void pool_kernel(const int* __restrict__ batch, int n) {
    int nn = blockIdx.x * blockDim.x + threadIdx.x;
    if (nn >= n) return;
    int g = batch[nn];
    const float4* ac = (const float4*)(g_acc + (size_t)nn * HH);
    const float4* xr = (const float4*)(g_X + (size_t)nn * XP);
    float* gs = g_gsum + (size_t)g * (HH + XP);
#pragma unroll
    for (int q = 0; q < 8; q++) {
        float4 v = ac[q];
        red_add_v4(gs + 4 * q, v.x, v.y, v.z, v.w);
    }
#pragma unroll
    for (int q = 0; q < 4; q++) {
        float4 v = xr[q];
        red_add_v4(gs + HH + 4 * q, v.x, v.y, v.z, v.w);
    }
    atomicAdd(&g_gcnt[g], 1);
}

// ---------------- 7) output MLP + sigmoid ----------------
__global__ void out_kernel(const float* __restrict__ w1,
                           const float* __restrict__ b1,
                           const float* __restrict__ w2,
                           const float* __restrict__ b2,
                           float* __restrict__ out, int gcount) {
    int g = blockIdx.x * blockDim.x + threadIdx.x;
    if (g >= gcount) return;
    float cnt = fmaxf((float)g_gcnt[g], 1.f);
    float inv = 1.f / cnt;
    float m[FF];
#pragma unroll
    for (int a = 0; a < FF; a++) m[a] = g_gsum[g * (HH + XP) + a] * inv;
    float o = b2[0];
    for (int h = 0; h < HH; h++) {
        float t = b1[h];
#pragma unroll
        for (int a = 0; a < FF; a++) t = fmaf(m[a], w1[a * HH + h], t);
        o = fmaf(fmaxf(t, 0.f), w2[h], o);
    }
    out[g] = 1.f / (1.f + expf(-o));
}

// ---------------- launch ----------------
extern "C" void kernel_launch(void* const* d_in, const int* in_sizes, int n_in,
                              void* d_out, int out_size) {
    const float* x     = (const float*)d_in[0];
    const int*   ei    = (const int*)d_in[1];
    const int*   batch = (const int*)d_in[2];
    const float* gamma = (const float*)d_in[3];
    const float* beta  = (const float*)d_in[4];
    const float* in_w1 = (const float*)d_in[5];
    const float* in_b1 = (const float*)d_in[6];
    const float* in_w2 = (const float*)d_in[7];
    const float* in_b2 = (const float*)d_in[8];
    const float* cw1   = (const float*)d_in[9];
    const float* cb1   = (const float*)d_in[10];
    const float* cw2   = (const float*)d_in[11];
    const float* cb2   = (const float*)d_in[12];
    const float* ow1   = (const float*)d_in[13];
    const float* ob1   = (const float*)d_in[14];
    const float* ow2   = (const float*)d_in[15];
    const float* ob2   = (const float*)d_in[16];

    int n = in_sizes[0] / DD;
    int E = in_sizes[1] / 2;
    int G = out_size;
    int ntiles = (E + TILE - 1) / TILE;
    int grid = 592;
    if (grid > ntiles) grid = ntiles;

    zero_kernel<<<1, 256>>>();
    bn_stats<<<148, 256>>>(x, n);
    prep_kernel<<<1, 256>>>(cw1, 1.f / (float)n);
    node_kernel<<<(n + 127) / 128, 128>>>(x, gamma, beta, in_w1, in_b1,
                                          in_w2, in_b2, cb1, n);
    edge_kernel<<<grid, 256>>>(ei, cw2, cb2, E, ntiles);
    pool_kernel<<<(n + 255) / 256, 256>>>(batch, n);
    out_kernel<<<1, 128>>>(ow1, ob1, ow2, ob2, (float*)d_out, G);
}